// round 5
// baseline (speedup 1.0000x reference)
#include <cuda_runtime.h>
#include <cstdint>

#define N_NODES 100000
#define N_EDGES 1250000
#define D 64
#define SCAN_BLOCKS ((N_NODES + 255) / 256)   // 391
#define SROW 68   // padded smem row stride (floats)

// Scratch (static device globals — no allocation allowed)
__device__ float g_agg[(size_t)N_NODES * D];   // A1 = agg(x), 25.6 MB
__device__ float g_W2[D * D];                  // (W·W)
__device__ float g_bW[D];                      // b @ W^T
__device__ int   g_deg[N_NODES];
__device__ int   g_off[N_NODES + 1];
__device__ int   g_cur[N_NODES];
__device__ int   g_srcs[N_EDGES];
__device__ int   g_bsum[SCAN_BLOCKS];
__device__ int   g_boff[SCAN_BLOCKS];
__device__ int   g_is64;

// ---------------------------------------------------------------------------
// init: detect int64 vs int32 edge layout + zero degree counters
// ---------------------------------------------------------------------------
__global__ void init_kernel(const unsigned* __restrict__ ei) {
    int i = blockIdx.x * blockDim.x + threadIdx.x;
    if (i < N_NODES) g_deg[i] = 0;
    if (i == 0) {
        int all0 = 1;
        #pragma unroll 1
        for (int k = 0; k < 64; k++) {
            if (ei[2 * k + 1] != 0u) { all0 = 0; break; }
        }
        g_is64 = all0;
    }
}

__device__ __forceinline__ int load_idx(const void* ei, int pos) {
    if (g_is64) return (int)((const long long*)ei)[pos];
    return ((const int*)ei)[pos];
}

// ---------------------------------------------------------------------------
// prep: W2 = W @ W  (so out = A2 @ W2^T),  bW = b @ W^T
// ---------------------------------------------------------------------------
__global__ void prep_kernel(const float* __restrict__ W,
                            const float* __restrict__ b) {
    __shared__ float Wsh[D * D];
    int t = threadIdx.x;                 // 256
    #pragma unroll
    for (int i = t; i < D * D; i += 256) Wsh[i] = W[i];
    __syncthreads();
    #pragma unroll
    for (int i = t; i < D * D; i += 256) {
        int j = i >> 6, k = i & 63;
        float s = 0.f;
        #pragma unroll 8
        for (int m = 0; m < D; m++) s += Wsh[j * D + m] * Wsh[m * D + k];
        g_W2[i] = s;                     // W2[j][k] = sum_m W[j][m] W[m][k]
    }
    if (t < D) {
        float s = 0.f;
        #pragma unroll 8
        for (int k = 0; k < D; k++) s += b[k] * Wsh[t * D + k];
        g_bW[t] = s;
    }
}

// ---------------------------------------------------------------------------
// CSR build: histogram -> 3-phase scan -> fill
// ---------------------------------------------------------------------------
__global__ void hist_kernel(const void* __restrict__ ei) {
    int e = blockIdx.x * blockDim.x + threadIdx.x;
    if (e >= N_EDGES) return;
    int d = load_idx(ei, e + N_EDGES);
    atomicAdd(&g_deg[d], 1);
}

__global__ void partial_kernel() {
    __shared__ int ws[8];
    int t = threadIdx.x;
    int idx = blockIdx.x * 256 + t;
    int v = (idx < N_NODES) ? g_deg[idx] : 0;
    #pragma unroll
    for (int o = 16; o > 0; o >>= 1) v += __shfl_down_sync(0xffffffffu, v, o);
    if ((t & 31) == 0) ws[t >> 5] = v;
    __syncthreads();
    if (t == 0) {
        int s = 0;
        #pragma unroll
        for (int i = 0; i < 8; i++) s += ws[i];
        g_bsum[blockIdx.x] = s;
    }
}

__global__ void scan_bsums_kernel() {
    __shared__ int ws[16];
    int t = threadIdx.x;           // 512 threads
    int lane = t & 31, wid = t >> 5;
    int v = (t < SCAN_BLOCKS) ? g_bsum[t] : 0;
    int incl = v;
    #pragma unroll
    for (int o = 1; o < 32; o <<= 1) {
        int n = __shfl_up_sync(0xffffffffu, incl, o);
        if (lane >= o) incl += n;
    }
    if (lane == 31) ws[wid] = incl;
    __syncthreads();
    if (wid == 0) {
        int w = (lane < 16) ? ws[lane] : 0;
        #pragma unroll
        for (int o = 1; o < 16; o <<= 1) {
            int n = __shfl_up_sync(0xffffffffu, w, o);
            if (lane >= o) w += n;
        }
        if (lane < 16) ws[lane] = w;
    }
    __syncthreads();
    int excl = incl - v + (wid ? ws[wid - 1] : 0);
    if (t < SCAN_BLOCKS) g_boff[t] = excl;
    if (t == 0) g_off[N_NODES] = N_EDGES;
}

__global__ void write_off_kernel() {
    __shared__ int ws[8];
    int t = threadIdx.x;
    int lane = t & 31, wid = t >> 5;
    int idx = blockIdx.x * 256 + t;
    int v = (idx < N_NODES) ? g_deg[idx] : 0;
    int incl = v;
    #pragma unroll
    for (int o = 1; o < 32; o <<= 1) {
        int n = __shfl_up_sync(0xffffffffu, incl, o);
        if (lane >= o) incl += n;
    }
    if (lane == 31) ws[wid] = incl;
    __syncthreads();
    if (wid == 0) {
        int w = (lane < 8) ? ws[lane] : 0;
        #pragma unroll
        for (int o = 1; o < 8; o <<= 1) {
            int n = __shfl_up_sync(0xffffffffu, w, o);
            if (lane >= o) w += n;
        }
        if (lane < 8) ws[lane] = w;
    }
    __syncthreads();
    int excl = incl - v + (wid ? ws[wid - 1] : 0) + g_boff[blockIdx.x];
    if (idx < N_NODES) {
        g_off[idx] = excl;
        g_cur[idx] = excl;
    }
}

__global__ void fill_kernel(const void* __restrict__ ei) {
    int e = blockIdx.x * blockDim.x + threadIdx.x;
    if (e >= N_EDGES) return;
    int s = load_idx(ei, e);
    int d = load_idx(ei, e + N_EDGES);
    int pos = atomicAdd(&g_cur[d], 1);
    g_srcs[pos] = s;
}

// ---------------------------------------------------------------------------
// gather1: g_agg[i] = sum over incoming edges of x[src]. 16 lanes per node.
// ---------------------------------------------------------------------------
__global__ void gather_kernel(const float* __restrict__ h) {
    int t = blockIdx.x * blockDim.x + threadIdx.x;
    int node = t >> 4;
    int c = t & 15;
    if (node >= N_NODES) return;

    int beg = __ldg(&g_off[node]);
    int end = __ldg(&g_off[node + 1]);

    float4 acc = make_float4(0.f, 0.f, 0.f, 0.f);
    #pragma unroll 4
    for (int e = beg; e < end; e++) {
        int s = __ldg(&g_srcs[e]);
        float4 v = *reinterpret_cast<const float4*>(h + (size_t)s * D + c * 4);
        acc.x += v.x; acc.y += v.y; acc.z += v.z; acc.w += v.w;
    }
    *reinterpret_cast<float4*>(g_agg + (size_t)node * D + c * 4) = acc;
}

// ---------------------------------------------------------------------------
// Fused dual kernel: per 64-node tile
//   phase 1:  hid = A1 @ W^T  + b
//   phase 2:  A2tile = gather(A1);  out = A2tile @ W2^T + deg*bW + b
// 4x4 register tile, fma.rn.f32x2 (FFMA2).
// ---------------------------------------------------------------------------
__global__ __launch_bounds__(256) void fused_kernel(
        float* __restrict__ hid, float* __restrict__ out,
        const float* __restrict__ W, const float* __restrict__ b) {
    __shared__ __align__(16) float As[64 * SROW];
    __shared__ __align__(16) float Ws[64 * SROW];

    const int t = threadIdx.x;           // 256 threads
    const int row0 = blockIdx.x * 64;
    const int tx = t & 15;
    const int ty = t >> 4;

    // ---- stage W and A1 tile ----
    #pragma unroll
    for (int i = t; i < 64 * 16; i += 256) {
        int j = i >> 4, k4 = i & 15;
        *reinterpret_cast<float4*>(&Ws[j * SROW + k4 * 4]) =
            reinterpret_cast<const float4*>(W)[j * 16 + k4];
    }
    #pragma unroll
    for (int i = t; i < 64 * 16; i += 256) {
        int r = i >> 4, k4 = i & 15;
        int row = row0 + r;
        float4 v = make_float4(0.f, 0.f, 0.f, 0.f);
        if (row < N_NODES)
            v = reinterpret_cast<const float4*>(g_agg)[(size_t)row * 16 + k4];
        *reinterpret_cast<float4*>(&As[r * SROW + k4 * 4]) = v;
    }
    __syncthreads();

    // ---- GEMM 1: hid = A1 @ W^T + b ----
    {
        unsigned long long acc[4][4];
        #pragma unroll
        for (int ri = 0; ri < 4; ri++)
            #pragma unroll
            for (int ji = 0; ji < 4; ji++) acc[ri][ji] = 0ull;

        #pragma unroll 4
        for (int k4 = 0; k4 < 16; k4++) {
            ulonglong2 a[4], w[4];
            #pragma unroll
            for (int ri = 0; ri < 4; ri++)
                a[ri] = *reinterpret_cast<const ulonglong2*>(&As[(ty * 4 + ri) * SROW + k4 * 4]);
            #pragma unroll
            for (int ji = 0; ji < 4; ji++)
                w[ji] = *reinterpret_cast<const ulonglong2*>(&Ws[(tx + 16 * ji) * SROW + k4 * 4]);
            #pragma unroll
            for (int ri = 0; ri < 4; ri++)
                #pragma unroll
                for (int ji = 0; ji < 4; ji++) {
                    asm("fma.rn.f32x2 %0, %1, %2, %0;"
                        : "+l"(acc[ri][ji]) : "l"(a[ri].x), "l"(w[ji].x));
                    asm("fma.rn.f32x2 %0, %1, %2, %0;"
                        : "+l"(acc[ri][ji]) : "l"(a[ri].y), "l"(w[ji].y));
                }
        }
        float bj[4];
        #pragma unroll
        for (int ji = 0; ji < 4; ji++) bj[ji] = __ldg(&b[tx + 16 * ji]);
        #pragma unroll
        for (int ri = 0; ri < 4; ri++) {
            int row = row0 + ty * 4 + ri;
            if (row < N_NODES) {
                #pragma unroll
                for (int ji = 0; ji < 4; ji++) {
                    float lo, hi;
                    asm("mov.b64 {%0, %1}, %2;" : "=f"(lo), "=f"(hi) : "l"(acc[ri][ji]));
                    hid[(size_t)row * D + tx + 16 * ji] = lo + hi + bj[ji];
                }
            }
        }
    }
    __syncthreads();   // everyone done reading As/Ws

    // ---- phase 2: re-stage Ws = W2, gather A2 tile into As ----
    #pragma unroll
    for (int i = t; i < 64 * 16; i += 256) {
        int j = i >> 4, k4 = i & 15;
        *reinterpret_cast<float4*>(&Ws[j * SROW + k4 * 4]) =
            reinterpret_cast<const float4*>(g_W2)[j * 16 + k4];
    }
    {
        const int c = t & 15;            // float4 chunk
        #pragma unroll
        for (int q = 0; q < 4; q++) {
            int rl = q * 16 + (t >> 4);  // local row 0..63
            int node = row0 + rl;
            float4 acc = make_float4(0.f, 0.f, 0.f, 0.f);
            if (node < N_NODES) {
                int beg = __ldg(&g_off[node]);
                int end = __ldg(&g_off[node + 1]);
                #pragma unroll 4
                for (int e = beg; e < end; e++) {
                    int s = __ldg(&g_srcs[e]);
                    float4 v = *reinterpret_cast<const float4*>(g_agg + (size_t)s * D + c * 4);
                    acc.x += v.x; acc.y += v.y; acc.z += v.z; acc.w += v.w;
                }
            }
            *reinterpret_cast<float4*>(&As[rl * SROW + c * 4]) = acc;
        }
    }
    __syncthreads();

    // ---- GEMM 2: out = A2 @ W2^T + deg*bW + b ----
    {
        unsigned long long acc[4][4];
        #pragma unroll
        for (int ri = 0; ri < 4; ri++)
            #pragma unroll
            for (int ji = 0; ji < 4; ji++) acc[ri][ji] = 0ull;

        #pragma unroll 4
        for (int k4 = 0; k4 < 16; k4++) {
            ulonglong2 a[4], w[4];
            #pragma unroll
            for (int ri = 0; ri < 4; ri++)
                a[ri] = *reinterpret_cast<const ulonglong2*>(&As[(ty * 4 + ri) * SROW + k4 * 4]);
            #pragma unroll
            for (int ji = 0; ji < 4; ji++)
                w[ji] = *reinterpret_cast<const ulonglong2*>(&Ws[(tx + 16 * ji) * SROW + k4 * 4]);
            #pragma unroll
            for (int ri = 0; ri < 4; ri++)
                #pragma unroll
                for (int ji = 0; ji < 4; ji++) {
                    asm("fma.rn.f32x2 %0, %1, %2, %0;"
                        : "+l"(acc[ri][ji]) : "l"(a[ri].x), "l"(w[ji].x));
                    asm("fma.rn.f32x2 %0, %1, %2, %0;"
                        : "+l"(acc[ri][ji]) : "l"(a[ri].y), "l"(w[ji].y));
                }
        }
        float bj[4], bWj[4];
        #pragma unroll
        for (int ji = 0; ji < 4; ji++) {
            bj[ji]  = __ldg(&b[tx + 16 * ji]);
            bWj[ji] = __ldg(&g_bW[tx + 16 * ji]);
        }
        #pragma unroll
        for (int ri = 0; ri < 4; ri++) {
            int row = row0 + ty * 4 + ri;
            if (row < N_NODES) {
                float degf = __int2float_rn(__ldg(&g_deg[row]));
                #pragma unroll
                for (int ji = 0; ji < 4; ji++) {
                    float lo, hi;
                    asm("mov.b64 {%0, %1}, %2;" : "=f"(lo), "=f"(hi) : "l"(acc[ri][ji]));
                    out[(size_t)row * D + tx + 16 * ji] = lo + hi + degf * bWj[ji] + bj[ji];
                }
            }
        }
    }
}

// ---------------------------------------------------------------------------
extern "C" void kernel_launch(void* const* d_in, const int* in_sizes, int n_in,
                              void* d_out, int out_size) {
    const float* x  = (const float*)d_in[0];
    const void*  ei = d_in[1];
    const float* W1 = (const float*)d_in[2];
    const float* b1 = (const float*)d_in[3];

    float* out = (float*)d_out;                      // (out, hid) flattened
    float* hid = out + (size_t)N_NODES * D;

    const int EBLK = (N_EDGES + 255) / 256;
    const int NBLK = (N_NODES + 255) / 256;
    const int GBLK = (N_NODES * 16 + 255) / 256;     // 6250
    const int FBLK = (N_NODES + 63) / 64;            // 1563

    init_kernel<<<NBLK, 256>>>((const unsigned*)ei);
    prep_kernel<<<1, 256>>>(W1, b1);

    hist_kernel<<<EBLK, 256>>>(ei);
    partial_kernel<<<SCAN_BLOCKS, 256>>>();
    scan_bsums_kernel<<<1, 512>>>();
    write_off_kernel<<<SCAN_BLOCKS, 256>>>();
    fill_kernel<<<EBLK, 256>>>(ei);

    gather_kernel<<<GBLK, 256>>>(x);                 // A1 = agg(x)
    fused_kernel<<<FBLK, 256>>>(hid, out, W1, b1);   // hid + out
}

// round 7
// speedup vs baseline: 1.0031x; 1.0031x over previous
#include <cuda_runtime.h>
#include <cuda_fp16.h>
#include <cstdint>

#define N_NODES 100000
#define N_EDGES 1250000
#define D 64
#define SCAN_BLOCKS ((N_NODES + 255) / 256)   // 391
#define SROW 68   // padded smem row stride (floats)

// Scratch (static device globals — no allocation allowed)
__device__ __align__(128) __half g_xh[(size_t)N_NODES * D];   // fp16 x
__device__ __align__(128) __half g_a1h[(size_t)N_NODES * D];  // fp16 A1=agg(x)
__device__ __align__(128) float  g_a2f[(size_t)N_NODES * D];  // fp32 A2=agg(A1)
__device__ float g_W2[D * D];                  // W @ W
__device__ float g_bW[D];                      // b @ W^T
__device__ int   g_deg[N_NODES];
__device__ int   g_off[N_NODES + 1];
__device__ int   g_cur[N_NODES];
__device__ int   g_srcs[N_EDGES];
__device__ int   g_bsum[SCAN_BLOCKS];
__device__ int   g_boff[SCAN_BLOCKS];
__device__ int   g_is64;

// ---------------------------------------------------------------------------
// init: detect int64 vs int32 edge layout + zero degree counters
// ---------------------------------------------------------------------------
__global__ void init_kernel(const unsigned* __restrict__ ei) {
    int i = blockIdx.x * blockDim.x + threadIdx.x;
    if (i < N_NODES) g_deg[i] = 0;
    if (i == 0) {
        int all0 = 1;
        #pragma unroll 1
        for (int k = 0; k < 64; k++) {
            if (ei[2 * k + 1] != 0u) { all0 = 0; break; }
        }
        g_is64 = all0;
    }
}

__device__ __forceinline__ int load_idx(const void* ei, int pos) {
    if (g_is64) return (int)((const long long*)ei)[pos];
    return ((const int*)ei)[pos];
}

// ---------------------------------------------------------------------------
// prep: W2 = W @ W,  bW = b @ W^T
// ---------------------------------------------------------------------------
__global__ void prep_kernel(const float* __restrict__ W,
                            const float* __restrict__ b) {
    __shared__ float Wsh[D * D];
    int t = threadIdx.x;                 // 256
    #pragma unroll
    for (int i = t; i < D * D; i += 256) Wsh[i] = W[i];
    __syncthreads();
    #pragma unroll
    for (int i = t; i < D * D; i += 256) {
        int j = i >> 6, k = i & 63;
        float s = 0.f;
        #pragma unroll 8
        for (int m = 0; m < D; m++) s += Wsh[j * D + m] * Wsh[m * D + k];
        g_W2[i] = s;
    }
    if (t < D) {
        float s = 0.f;
        #pragma unroll 8
        for (int k = 0; k < D; k++) s += b[k] * Wsh[t * D + k];
        g_bW[t] = s;
    }
}

// ---------------------------------------------------------------------------
// convert x (fp32 input) -> g_xh (fp16). One thread per 8 elements.
// ---------------------------------------------------------------------------
__global__ void convert_kernel(const float* __restrict__ x) {
    int i = blockIdx.x * blockDim.x + threadIdx.x;   // over N*D/8
    const int n = N_NODES * D / 8;
    if (i >= n) return;
    float4 a = reinterpret_cast<const float4*>(x)[2 * i];
    float4 c = reinterpret_cast<const float4*>(x)[2 * i + 1];
    __half2 h0 = __floats2half2_rn(a.x, a.y);
    __half2 h1 = __floats2half2_rn(a.z, a.w);
    __half2 h2 = __floats2half2_rn(c.x, c.y);
    __half2 h3 = __floats2half2_rn(c.z, c.w);
    uint4 o;
    o.x = *reinterpret_cast<unsigned*>(&h0);
    o.y = *reinterpret_cast<unsigned*>(&h1);
    o.z = *reinterpret_cast<unsigned*>(&h2);
    o.w = *reinterpret_cast<unsigned*>(&h3);
    reinterpret_cast<uint4*>(g_xh)[i] = o;
}

// ---------------------------------------------------------------------------
// CSR build: histogram -> 3-phase scan -> fill
// ---------------------------------------------------------------------------
__global__ void hist_kernel(const void* __restrict__ ei) {
    int e = blockIdx.x * blockDim.x + threadIdx.x;
    if (e >= N_EDGES) return;
    int d = load_idx(ei, e + N_EDGES);
    atomicAdd(&g_deg[d], 1);
}

__global__ void partial_kernel() {
    __shared__ int ws[8];
    int t = threadIdx.x;
    int idx = blockIdx.x * 256 + t;
    int v = (idx < N_NODES) ? g_deg[idx] : 0;
    #pragma unroll
    for (int o = 16; o > 0; o >>= 1) v += __shfl_down_sync(0xffffffffu, v, o);
    if ((t & 31) == 0) ws[t >> 5] = v;
    __syncthreads();
    if (t == 0) {
        int s = 0;
        #pragma unroll
        for (int i = 0; i < 8; i++) s += ws[i];
        g_bsum[blockIdx.x] = s;
    }
}

__global__ void scan_bsums_kernel() {
    __shared__ int ws[16];
    int t = threadIdx.x;           // 512 threads
    int lane = t & 31, wid = t >> 5;
    int v = (t < SCAN_BLOCKS) ? g_bsum[t] : 0;
    int incl = v;
    #pragma unroll
    for (int o = 1; o < 32; o <<= 1) {
        int n = __shfl_up_sync(0xffffffffu, incl, o);
        if (lane >= o) incl += n;
    }
    if (lane == 31) ws[wid] = incl;
    __syncthreads();
    if (wid == 0) {
        int w = (lane < 16) ? ws[lane] : 0;
        #pragma unroll
        for (int o = 1; o < 16; o <<= 1) {
            int n = __shfl_up_sync(0xffffffffu, w, o);
            if (lane >= o) w += n;
        }
        if (lane < 16) ws[lane] = w;
    }
    __syncthreads();
    int excl = incl - v + (wid ? ws[wid - 1] : 0);
    if (t < SCAN_BLOCKS) g_boff[t] = excl;
    if (t == 0) g_off[N_NODES] = N_EDGES;
}

__global__ void write_off_kernel() {
    __shared__ int ws[8];
    int t = threadIdx.x;
    int lane = t & 31, wid = t >> 5;
    int idx = blockIdx.x * 256 + t;
    int v = (idx < N_NODES) ? g_deg[idx] : 0;
    int incl = v;
    #pragma unroll
    for (int o = 1; o < 32; o <<= 1) {
        int n = __shfl_up_sync(0xffffffffu, incl, o);
        if (lane >= o) incl += n;
    }
    if (lane == 31) ws[wid] = incl;
    __syncthreads();
    if (wid == 0) {
        int w = (lane < 8) ? ws[lane] : 0;
        #pragma unroll
        for (int o = 1; o < 8; o <<= 1) {
            int n = __shfl_up_sync(0xffffffffu, w, o);
            if (lane >= o) w += n;
        }
        if (lane < 8) ws[lane] = w;
    }
    __syncthreads();
    int excl = incl - v + (wid ? ws[wid - 1] : 0) + g_boff[blockIdx.x];
    if (idx < N_NODES) {
        g_off[idx] = excl;
        g_cur[idx] = excl;
    }
}

__global__ void fill_kernel(const void* __restrict__ ei) {
    int e = blockIdx.x * blockDim.x + threadIdx.x;
    if (e >= N_EDGES) return;
    int s = load_idx(ei, e);
    int d = load_idx(ei, e + N_EDGES);
    int pos = atomicAdd(&g_cur[d], 1);
    g_srcs[pos] = s;
}

// ---------------------------------------------------------------------------
// Gather (fp16 reads, fp32 accumulate). Buffers selected IN DEVICE CODE.
//   phase 0: g_xh  -> g_a1h (fp16 out)
//   phase 1: g_a1h -> g_a2f (fp32 out)
// 8 lanes per node, each lane owns 8 halfs (uint4 = 16B). Row = 128B = 1 line.
// ---------------------------------------------------------------------------
__global__ void gather_h_kernel(int phase) {
    int t = blockIdx.x * blockDim.x + threadIdx.x;
    int node = t >> 3;
    int c = t & 7;
    if (node >= N_NODES) return;

    const __half* in = phase ? g_a1h : g_xh;

    int beg = __ldg(&g_off[node]);
    int end = __ldg(&g_off[node + 1]);

    float2 a0 = make_float2(0.f, 0.f), a1 = a0, a2 = a0, a3 = a0;
    #pragma unroll 4
    for (int e = beg; e < end; e++) {
        int s = __ldg(&g_srcs[e]);
        uint4 v = *reinterpret_cast<const uint4*>(in + (size_t)s * D + c * 8);
        float2 f0 = __half22float2(*reinterpret_cast<__half2*>(&v.x));
        float2 f1 = __half22float2(*reinterpret_cast<__half2*>(&v.y));
        float2 f2 = __half22float2(*reinterpret_cast<__half2*>(&v.z));
        float2 f3 = __half22float2(*reinterpret_cast<__half2*>(&v.w));
        a0.x += f0.x; a0.y += f0.y;
        a1.x += f1.x; a1.y += f1.y;
        a2.x += f2.x; a2.y += f2.y;
        a3.x += f3.x; a3.y += f3.y;
    }

    if (phase == 0) {
        __half2 h0 = __floats2half2_rn(a0.x, a0.y);
        __half2 h1 = __floats2half2_rn(a1.x, a1.y);
        __half2 h2 = __floats2half2_rn(a2.x, a2.y);
        __half2 h3 = __floats2half2_rn(a3.x, a3.y);
        uint4 o;
        o.x = *reinterpret_cast<unsigned*>(&h0);
        o.y = *reinterpret_cast<unsigned*>(&h1);
        o.z = *reinterpret_cast<unsigned*>(&h2);
        o.w = *reinterpret_cast<unsigned*>(&h3);
        *reinterpret_cast<uint4*>(g_a1h + (size_t)node * D + c * 8) = o;
    } else {
        float* dst = g_a2f + (size_t)node * D + c * 8;
        *reinterpret_cast<float4*>(dst)     = make_float4(a0.x, a0.y, a1.x, a1.y);
        *reinterpret_cast<float4*>(dst + 4) = make_float4(a2.x, a2.y, a3.x, a3.y);
    }
}

// ---------------------------------------------------------------------------
// Dual GEMM: per 64-row tile,
//   phase 1:  hid = A1 @ W^T  + b          (A1 fp16 -> fp32 smem)
//   phase 2:  out = A2 @ W2^T + deg*bW + b (A2 fp32)
// 4x4 register tile, fma.rn.f32x2 (FFMA2).
// ---------------------------------------------------------------------------
__device__ __forceinline__ void stage_a_tile_h(float* As, int row0, int t) {
    #pragma unroll
    for (int i = t; i < 64 * 8; i += 256) {      // 8 uint4 per row
        int r = i >> 3, c8 = i & 7;
        int row = row0 + r;
        float4 lo = make_float4(0.f, 0.f, 0.f, 0.f), hi = lo;
        if (row < N_NODES) {
            uint4 v = *reinterpret_cast<const uint4*>(g_a1h + (size_t)row * D + c8 * 8);
            float2 f0 = __half22float2(*reinterpret_cast<__half2*>(&v.x));
            float2 f1 = __half22float2(*reinterpret_cast<__half2*>(&v.y));
            float2 f2 = __half22float2(*reinterpret_cast<__half2*>(&v.z));
            float2 f3 = __half22float2(*reinterpret_cast<__half2*>(&v.w));
            lo = make_float4(f0.x, f0.y, f1.x, f1.y);
            hi = make_float4(f2.x, f2.y, f3.x, f3.y);
        }
        *reinterpret_cast<float4*>(&As[r * SROW + c8 * 8])     = lo;
        *reinterpret_cast<float4*>(&As[r * SROW + c8 * 8 + 4]) = hi;
    }
}

__device__ __forceinline__ void stage_a_tile_f(float* As, int row0, int t) {
    #pragma unroll
    for (int i = t; i < 64 * 16; i += 256) {
        int r = i >> 4, k4 = i & 15;
        int row = row0 + r;
        float4 v = make_float4(0.f, 0.f, 0.f, 0.f);
        if (row < N_NODES)
            v = reinterpret_cast<const float4*>(g_a2f)[(size_t)row * 16 + k4];
        *reinterpret_cast<float4*>(&As[r * SROW + k4 * 4]) = v;
    }
}

__device__ __forceinline__ void gemm_tile(const float* As, const float* Ws,
                                          unsigned long long acc[4][4],
                                          int tx, int ty) {
    #pragma unroll 4
    for (int k4 = 0; k4 < 16; k4++) {
        ulonglong2 a[4], w[4];
        #pragma unroll
        for (int ri = 0; ri < 4; ri++)
            a[ri] = *reinterpret_cast<const ulonglong2*>(&As[(ty * 4 + ri) * SROW + k4 * 4]);
        #pragma unroll
        for (int ji = 0; ji < 4; ji++)
            w[ji] = *reinterpret_cast<const ulonglong2*>(&Ws[(tx + 16 * ji) * SROW + k4 * 4]);
        #pragma unroll
        for (int ri = 0; ri < 4; ri++)
            #pragma unroll
            for (int ji = 0; ji < 4; ji++) {
                asm("fma.rn.f32x2 %0, %1, %2, %0;"
                    : "+l"(acc[ri][ji]) : "l"(a[ri].x), "l"(w[ji].x));
                asm("fma.rn.f32x2 %0, %1, %2, %0;"
                    : "+l"(acc[ri][ji]) : "l"(a[ri].y), "l"(w[ji].y));
            }
    }
}

__global__ __launch_bounds__(256) void dual_linear_kernel(
        float* __restrict__ hid, float* __restrict__ out,
        const float* __restrict__ W, const float* __restrict__ b) {
    __shared__ __align__(16) float As[64 * SROW];
    __shared__ __align__(16) float Ws[64 * SROW];

    const int t = threadIdx.x;           // 256 threads
    const int row0 = blockIdx.x * 64;
    const int tx = t & 15;
    const int ty = t >> 4;

    // ---- phase 1: hid = A1 @ W^T + b ----
    #pragma unroll
    for (int i = t; i < 64 * 16; i += 256) {
        int j = i >> 4, k4 = i & 15;
        *reinterpret_cast<float4*>(&Ws[j * SROW + k4 * 4]) =
            reinterpret_cast<const float4*>(W)[j * 16 + k4];
    }
    stage_a_tile_h(As, row0, t);
    __syncthreads();

    {
        unsigned long long acc[4][4];
        #pragma unroll
        for (int ri = 0; ri < 4; ri++)
            #pragma unroll
            for (int ji = 0; ji < 4; ji++) acc[ri][ji] = 0ull;
        gemm_tile(As, Ws, acc, tx, ty);
        float bj[4];
        #pragma unroll
        for (int ji = 0; ji < 4; ji++) bj[ji] = __ldg(&b[tx + 16 * ji]);
        #pragma unroll
        for (int ri = 0; ri < 4; ri++) {
            int row = row0 + ty * 4 + ri;
            if (row < N_NODES) {
                #pragma unroll
                for (int ji = 0; ji < 4; ji++) {
                    float lo, hi;
                    asm("mov.b64 {%0, %1}, %2;" : "=f"(lo), "=f"(hi) : "l"(acc[ri][ji]));
                    hid[(size_t)row * D + tx + 16 * ji] = lo + hi + bj[ji];
                }
            }
        }
    }
    __syncthreads();

    // ---- phase 2: out = A2 @ W2^T + deg*bW + b ----
    #pragma unroll
    for (int i = t; i < 64 * 16; i += 256) {
        int j = i >> 4, k4 = i & 15;
        *reinterpret_cast<float4*>(&Ws[j * SROW + k4 * 4]) =
            reinterpret_cast<const float4*>(g_W2)[j * 16 + k4];
    }
    stage_a_tile_f(As, row0, t);
    __syncthreads();

    {
        unsigned long long acc[4][4];
        #pragma unroll
        for (int ri = 0; ri < 4; ri++)
            #pragma unroll
            for (int ji = 0; ji < 4; ji++) acc[ri][ji] = 0ull;
        gemm_tile(As, Ws, acc, tx, ty);
        float bj[4], bWj[4];
        #pragma unroll
        for (int ji = 0; ji < 4; ji++) {
            bj[ji]  = __ldg(&b[tx + 16 * ji]);
            bWj[ji] = __ldg(&g_bW[tx + 16 * ji]);
        }
        #pragma unroll
        for (int ri = 0; ri < 4; ri++) {
            int row = row0 + ty * 4 + ri;
            if (row < N_NODES) {
                float degf = __int2float_rn(__ldg(&g_deg[row]));
                #pragma unroll
                for (int ji = 0; ji < 4; ji++) {
                    float lo, hi;
                    asm("mov.b64 {%0, %1}, %2;" : "=f"(lo), "=f"(hi) : "l"(acc[ri][ji]));
                    out[(size_t)row * D + tx + 16 * ji] = lo + hi + degf * bWj[ji] + bj[ji];
                }
            }
        }
    }
}

// ---------------------------------------------------------------------------
extern "C" void kernel_launch(void* const* d_in, const int* in_sizes, int n_in,
                              void* d_out, int out_size) {
    const float* x  = (const float*)d_in[0];
    const void*  ei = d_in[1];
    const float* W1 = (const float*)d_in[2];
    const float* b1 = (const float*)d_in[3];

    float* out = (float*)d_out;                      // (out, hid) flattened
    float* hid = out + (size_t)N_NODES * D;

    const int EBLK = (N_EDGES + 255) / 256;
    const int NBLK = (N_NODES + 255) / 256;
    const int CBLK = (N_NODES * D / 8 + 255) / 256;
    const int GBLK = (N_NODES * 8 + 255) / 256;      // 3125
    const int FBLK = (N_NODES + 63) / 64;            // 1563

    init_kernel<<<NBLK, 256>>>((const unsigned*)ei);
    prep_kernel<<<1, 256>>>(W1, b1);
    convert_kernel<<<CBLK, 256>>>(x);

    hist_kernel<<<EBLK, 256>>>(ei);
    partial_kernel<<<SCAN_BLOCKS, 256>>>();
    scan_bsums_kernel<<<1, 512>>>();
    write_off_kernel<<<SCAN_BLOCKS, 256>>>();
    fill_kernel<<<EBLK, 256>>>(ei);

    gather_h_kernel<<<GBLK, 256>>>(0);               // A1 = agg(x)   (fp16)
    gather_h_kernel<<<GBLK, 256>>>(1);               // A2 = agg(A1)  (fp32)
    dual_linear_kernel<<<FBLK, 256>>>(hid, out, W1, b1);
}

// round 8
// speedup vs baseline: 1.0595x; 1.0562x over previous
#include <cuda_runtime.h>
#include <cstdint>

#define N_NODES 100000
#define N_EDGES 1250000
#define D 64
#define SCAN_BLOCKS ((N_NODES + 255) / 256)   // 391
#define SROW 68   // padded smem row stride (floats)

// Scratch (static device globals — no allocation allowed)
__device__ __align__(128) float g_a1[(size_t)N_NODES * D];  // A1 = agg(x)
__device__ __align__(128) float g_a2[(size_t)N_NODES * D];  // A2 = agg(A1)
__device__ float g_W2[D * D];                  // W @ W
__device__ float g_bW[D];                      // b @ W^T
__device__ int   g_deg[N_NODES];
__device__ int   g_off[N_NODES + 1];
__device__ int   g_cur[N_NODES];
__device__ int   g_srcs[N_EDGES];
__device__ int   g_bsum[SCAN_BLOCKS];
__device__ int   g_boff[SCAN_BLOCKS];
__device__ int   g_is64;

// ---------------------------------------------------------------------------
// init: detect int64 vs int32 edge layout + zero degree counters
// ---------------------------------------------------------------------------
__global__ void init_kernel(const unsigned* __restrict__ ei) {
    int i = blockIdx.x * blockDim.x + threadIdx.x;
    if (i < N_NODES) g_deg[i] = 0;
    if (i == 0) {
        int all0 = 1;
        #pragma unroll 1
        for (int k = 0; k < 64; k++) {
            if (ei[2 * k + 1] != 0u) { all0 = 0; break; }
        }
        g_is64 = all0;
    }
}

// ---------------------------------------------------------------------------
// prep (parallel, 17 blocks): W2 = W @ W,  bW = b @ W^T
// ---------------------------------------------------------------------------
__global__ void prep_kernel(const float* __restrict__ W,
                            const float* __restrict__ b) {
    __shared__ float Wsh[D * D];
    int t = threadIdx.x;                 // 256
    #pragma unroll
    for (int i = t; i < D * D; i += 256) Wsh[i] = W[i];
    __syncthreads();
    if (blockIdx.x < 16) {
        int o = blockIdx.x * 256 + t;
        int j = o >> 6, k = o & 63;
        float s = 0.f;
        #pragma unroll
        for (int m = 0; m < D; m++) s += Wsh[j * D + m] * Wsh[m * D + k];
        g_W2[o] = s;
    } else if (t < D) {
        float s = 0.f;
        #pragma unroll
        for (int k = 0; k < D; k++) s += b[k] * Wsh[t * D + k];
        g_bW[t] = s;
    }
}

// ---------------------------------------------------------------------------
// CSR build: histogram (4 edges/thread) -> 3-phase scan -> fill (4/thread)
// ---------------------------------------------------------------------------
__global__ void hist_kernel(const void* __restrict__ ei) {
    int q = blockIdx.x * blockDim.x + threadIdx.x;
    int e = q * 4;
    if (e >= N_EDGES) return;
    int d0, d1, d2, d3;
    if (g_is64) {
        const longlong2* p = reinterpret_cast<const longlong2*>(
            (const long long*)ei + N_EDGES + e);
        longlong2 a = __ldg(p), c = __ldg(p + 1);
        d0 = (int)a.x; d1 = (int)a.y; d2 = (int)c.x; d3 = (int)c.y;
    } else {
        int4 a = __ldg(reinterpret_cast<const int4*>((const int*)ei + N_EDGES + e));
        d0 = a.x; d1 = a.y; d2 = a.z; d3 = a.w;
    }
    atomicAdd(&g_deg[d0], 1);
    atomicAdd(&g_deg[d1], 1);
    atomicAdd(&g_deg[d2], 1);
    atomicAdd(&g_deg[d3], 1);
}

__global__ void partial_kernel() {
    __shared__ int ws[8];
    int t = threadIdx.x;
    int idx = blockIdx.x * 256 + t;
    int v = (idx < N_NODES) ? g_deg[idx] : 0;
    #pragma unroll
    for (int o = 16; o > 0; o >>= 1) v += __shfl_down_sync(0xffffffffu, v, o);
    if ((t & 31) == 0) ws[t >> 5] = v;
    __syncthreads();
    if (t == 0) {
        int s = 0;
        #pragma unroll
        for (int i = 0; i < 8; i++) s += ws[i];
        g_bsum[blockIdx.x] = s;
    }
}

__global__ void scan_bsums_kernel() {
    __shared__ int ws[16];
    int t = threadIdx.x;           // 512 threads
    int lane = t & 31, wid = t >> 5;
    int v = (t < SCAN_BLOCKS) ? g_bsum[t] : 0;
    int incl = v;
    #pragma unroll
    for (int o = 1; o < 32; o <<= 1) {
        int n = __shfl_up_sync(0xffffffffu, incl, o);
        if (lane >= o) incl += n;
    }
    if (lane == 31) ws[wid] = incl;
    __syncthreads();
    if (wid == 0) {
        int w = (lane < 16) ? ws[lane] : 0;
        #pragma unroll
        for (int o = 1; o < 16; o <<= 1) {
            int n = __shfl_up_sync(0xffffffffu, w, o);
            if (lane >= o) w += n;
        }
        if (lane < 16) ws[lane] = w;
    }
    __syncthreads();
    int excl = incl - v + (wid ? ws[wid - 1] : 0);
    if (t < SCAN_BLOCKS) g_boff[t] = excl;
    if (t == 0) g_off[N_NODES] = N_EDGES;
}

__global__ void write_off_kernel() {
    __shared__ int ws[8];
    int t = threadIdx.x;
    int lane = t & 31, wid = t >> 5;
    int idx = blockIdx.x * 256 + t;
    int v = (idx < N_NODES) ? g_deg[idx] : 0;
    int incl = v;
    #pragma unroll
    for (int o = 1; o < 32; o <<= 1) {
        int n = __shfl_up_sync(0xffffffffu, incl, o);
        if (lane >= o) incl += n;
    }
    if (lane == 31) ws[wid] = incl;
    __syncthreads();
    if (wid == 0) {
        int w = (lane < 8) ? ws[lane] : 0;
        #pragma unroll
        for (int o = 1; o < 8; o <<= 1) {
            int n = __shfl_up_sync(0xffffffffu, w, o);
            if (lane >= o) w += n;
        }
        if (lane < 8) ws[lane] = w;
    }
    __syncthreads();
    int excl = incl - v + (wid ? ws[wid - 1] : 0) + g_boff[blockIdx.x];
    if (idx < N_NODES) {
        g_off[idx] = excl;
        g_cur[idx] = excl;
    }
}

__global__ void fill_kernel(const void* __restrict__ ei) {
    int q = blockIdx.x * blockDim.x + threadIdx.x;
    int e = q * 4;
    if (e >= N_EDGES) return;
    int s0, s1, s2, s3, d0, d1, d2, d3;
    if (g_is64) {
        const longlong2* ps = reinterpret_cast<const longlong2*>((const long long*)ei + e);
        const longlong2* pd = reinterpret_cast<const longlong2*>((const long long*)ei + N_EDGES + e);
        longlong2 a = __ldg(ps), c = __ldg(ps + 1);
        longlong2 u = __ldg(pd), w = __ldg(pd + 1);
        s0 = (int)a.x; s1 = (int)a.y; s2 = (int)c.x; s3 = (int)c.y;
        d0 = (int)u.x; d1 = (int)u.y; d2 = (int)w.x; d3 = (int)w.y;
    } else {
        int4 a = __ldg(reinterpret_cast<const int4*>((const int*)ei + e));
        int4 u = __ldg(reinterpret_cast<const int4*>((const int*)ei + N_EDGES + e));
        s0 = a.x; s1 = a.y; s2 = a.z; s3 = a.w;
        d0 = u.x; d1 = u.y; d2 = u.z; d3 = u.w;
    }
    g_srcs[atomicAdd(&g_cur[d0], 1)] = s0;
    g_srcs[atomicAdd(&g_cur[d1], 1)] = s1;
    g_srcs[atomicAdd(&g_cur[d2], 1)] = s2;
    g_srcs[atomicAdd(&g_cur[d3], 1)] = s3;
}

// ---------------------------------------------------------------------------
// Gather (fp32): phase 0: x -> g_a1, phase 1: g_a1 -> g_a2.
// 16 lanes per node (one float4 each). 8-edge software pipeline: batch-load
// 8 src indices, then 8 independent rows (MLP=8), then accumulate.
// ---------------------------------------------------------------------------
__global__ void gather_kernel(const float* __restrict__ x, int phase) {
    int t = blockIdx.x * blockDim.x + threadIdx.x;
    int node = t >> 4;
    int c = t & 15;
    if (node >= N_NODES) return;

    const float* in = phase ? g_a1 : x;
    float* outp     = phase ? g_a2 : g_a1;

    int beg = __ldg(&g_off[node]);
    int end = __ldg(&g_off[node + 1]);

    float4 acc = make_float4(0.f, 0.f, 0.f, 0.f);
    int e = beg;
    for (; e + 8 <= end; e += 8) {
        int s[8];
        #pragma unroll
        for (int i = 0; i < 8; i++) s[i] = __ldg(&g_srcs[e + i]);
        float4 v[8];
        #pragma unroll
        for (int i = 0; i < 8; i++)
            v[i] = *reinterpret_cast<const float4*>(in + (size_t)s[i] * D + c * 4);
        #pragma unroll
        for (int i = 0; i < 8; i++) {
            acc.x += v[i].x; acc.y += v[i].y; acc.z += v[i].z; acc.w += v[i].w;
        }
    }
    #pragma unroll 4
    for (; e < end; e++) {
        int s = __ldg(&g_srcs[e]);
        float4 v = *reinterpret_cast<const float4*>(in + (size_t)s * D + c * 4);
        acc.x += v.x; acc.y += v.y; acc.z += v.z; acc.w += v.w;
    }
    *reinterpret_cast<float4*>(outp + (size_t)node * D + c * 4) = acc;
}

// ---------------------------------------------------------------------------
// Dual GEMM per 64-row tile:
//   phase 1:  hid = A1 @ W^T  + b
//   phase 2:  out = A2 @ W2^T + deg*bW + b
// 4x4 register tile, fma.rn.f32x2 (FFMA2).
// ---------------------------------------------------------------------------
__device__ __forceinline__ void stage_a_tile(float* As, const float* __restrict__ src,
                                             int row0, int t) {
    #pragma unroll
    for (int i = t; i < 64 * 16; i += 256) {
        int r = i >> 4, k4 = i & 15;
        int row = row0 + r;
        float4 v = make_float4(0.f, 0.f, 0.f, 0.f);
        if (row < N_NODES)
            v = reinterpret_cast<const float4*>(src)[(size_t)row * 16 + k4];
        *reinterpret_cast<float4*>(&As[r * SROW + k4 * 4]) = v;
    }
}

__device__ __forceinline__ void gemm_tile(const float* As, const float* Ws,
                                          unsigned long long acc[4][4],
                                          int tx, int ty) {
    #pragma unroll 4
    for (int k4 = 0; k4 < 16; k4++) {
        ulonglong2 a[4], w[4];
        #pragma unroll
        for (int ri = 0; ri < 4; ri++)
            a[ri] = *reinterpret_cast<const ulonglong2*>(&As[(ty * 4 + ri) * SROW + k4 * 4]);
        #pragma unroll
        for (int ji = 0; ji < 4; ji++)
            w[ji] = *reinterpret_cast<const ulonglong2*>(&Ws[(tx + 16 * ji) * SROW + k4 * 4]);
        #pragma unroll
        for (int ri = 0; ri < 4; ri++)
            #pragma unroll
            for (int ji = 0; ji < 4; ji++) {
                asm("fma.rn.f32x2 %0, %1, %2, %0;"
                    : "+l"(acc[ri][ji]) : "l"(a[ri].x), "l"(w[ji].x));
                asm("fma.rn.f32x2 %0, %1, %2, %0;"
                    : "+l"(acc[ri][ji]) : "l"(a[ri].y), "l"(w[ji].y));
            }
    }
}

__global__ __launch_bounds__(256) void dual_linear_kernel(
        float* __restrict__ hid, float* __restrict__ out,
        const float* __restrict__ W, const float* __restrict__ b) {
    __shared__ __align__(16) float As[64 * SROW];
    __shared__ __align__(16) float Ws[64 * SROW];

    const int t = threadIdx.x;           // 256 threads
    const int row0 = blockIdx.x * 64;
    const int tx = t & 15;
    const int ty = t >> 4;

    // ---- phase 1: hid = A1 @ W^T + b ----
    #pragma unroll
    for (int i = t; i < 64 * 16; i += 256) {
        int j = i >> 4, k4 = i & 15;
        *reinterpret_cast<float4*>(&Ws[j * SROW + k4 * 4]) =
            reinterpret_cast<const float4*>(W)[j * 16 + k4];
    }
    stage_a_tile(As, g_a1, row0, t);
    __syncthreads();

    {
        unsigned long long acc[4][4];
        #pragma unroll
        for (int ri = 0; ri < 4; ri++)
            #pragma unroll
            for (int ji = 0; ji < 4; ji++) acc[ri][ji] = 0ull;
        gemm_tile(As, Ws, acc, tx, ty);
        float bj[4];
        #pragma unroll
        for (int ji = 0; ji < 4; ji++) bj[ji] = __ldg(&b[tx + 16 * ji]);
        #pragma unroll
        for (int ri = 0; ri < 4; ri++) {
            int row = row0 + ty * 4 + ri;
            if (row < N_NODES) {
                #pragma unroll
                for (int ji = 0; ji < 4; ji++) {
                    float lo, hi;
                    asm("mov.b64 {%0, %1}, %2;" : "=f"(lo), "=f"(hi) : "l"(acc[ri][ji]));
                    hid[(size_t)row * D + tx + 16 * ji] = lo + hi + bj[ji];
                }
            }
        }
    }
    __syncthreads();

    // ---- phase 2: out = A2 @ W2^T + deg*bW + b ----
    #pragma unroll
    for (int i = t; i < 64 * 16; i += 256) {
        int j = i >> 4, k4 = i & 15;
        *reinterpret_cast<float4*>(&Ws[j * SROW + k4 * 4]) =
            reinterpret_cast<const float4*>(g_W2)[j * 16 + k4];
    }
    stage_a_tile(As, g_a2, row0, t);
    __syncthreads();

    {
        unsigned long long acc[4][4];
        #pragma unroll
        for (int ri = 0; ri < 4; ri++)
            #pragma unroll
            for (int ji = 0; ji < 4; ji++) acc[ri][ji] = 0ull;
        gemm_tile(As, Ws, acc, tx, ty);
        float bj[4], bWj[4];
        #pragma unroll
        for (int ji = 0; ji < 4; ji++) {
            bj[ji]  = __ldg(&b[tx + 16 * ji]);
            bWj[ji] = __ldg(&g_bW[tx + 16 * ji]);
        }
        #pragma unroll
        for (int ri = 0; ri < 4; ri++) {
            int row = row0 + ty * 4 + ri;
            if (row < N_NODES) {
                float degf = __int2float_rn(__ldg(&g_deg[row]));
                #pragma unroll
                for (int ji = 0; ji < 4; ji++) {
                    float lo, hi;
                    asm("mov.b64 {%0, %1}, %2;" : "=f"(lo), "=f"(hi) : "l"(acc[ri][ji]));
                    out[(size_t)row * D + tx + 16 * ji] = lo + hi + degf * bWj[ji] + bj[ji];
                }
            }
        }
    }
}

// ---------------------------------------------------------------------------
extern "C" void kernel_launch(void* const* d_in, const int* in_sizes, int n_in,
                              void* d_out, int out_size) {
    const float* x  = (const float*)d_in[0];
    const void*  ei = d_in[1];
    const float* W1 = (const float*)d_in[2];
    const float* b1 = (const float*)d_in[3];

    float* out = (float*)d_out;                      // (out, hid) flattened
    float* hid = out + (size_t)N_NODES * D;

    const int E4BLK = (N_EDGES / 4 + 255) / 256;     // 1221
    const int NBLK  = (N_NODES + 255) / 256;
    const int GBLK  = (N_NODES * 16 + 255) / 256;    // 6250
    const int FBLK  = (N_NODES + 63) / 64;           // 1563

    init_kernel<<<NBLK, 256>>>((const unsigned*)ei);
    prep_kernel<<<17, 256>>>(W1, b1);

    hist_kernel<<<E4BLK, 256>>>(ei);
    partial_kernel<<<SCAN_BLOCKS, 256>>>();
    scan_bsums_kernel<<<1, 512>>>();
    write_off_kernel<<<SCAN_BLOCKS, 256>>>();
    fill_kernel<<<E4BLK, 256>>>(ei);

    gather_kernel<<<GBLK, 256>>>(x, 0);              // A1 = agg(x)
    gather_kernel<<<GBLK, 256>>>(x, 1);              // A2 = agg(A1)
    dual_linear_kernel<<<FBLK, 256>>>(hid, out, W1, b1);
}